// round 1
// baseline (speedup 1.0000x reference)
#include <cuda_runtime.h>
#include <cuda_bf16.h>

// Problem shape (fixed by the dataset):
//   X  : [4, 4096, 1024] f32
//   Wq/Wk/Wv : [1024, 1024] f32, bq/bk/bv : [1024] f32
//   out: [4, 4096, 1024] f32 = softmax((XWq+bq)(XWk+bk)^T / 32) (XWv+bv)

#define B_BATCH 4
#define SEQ     4096
#define DIM     1024
#define MTOT    (B_BATCH * SEQ)     // 16384

// ---------------------------------------------------------------------------
// Scratch: __device__ globals (allocation inside kernel_launch is forbidden).
// ---------------------------------------------------------------------------
__device__ float g_Q[(size_t)B_BATCH * SEQ * DIM];   // 64 MiB
__device__ float g_K[(size_t)B_BATCH * SEQ * DIM];   // 64 MiB
__device__ float g_V[(size_t)B_BATCH * SEQ * DIM];   // 64 MiB
__device__ float g_S[(size_t)B_BATCH * SEQ * SEQ];   // 268 MiB

// ---------------------------------------------------------------------------
// Tiled fp32 GEMM: C = scale * (A @ B[^T]) (+ bias)
//   A: [M, K] row-major
//   B: TRANS_B=0 -> [K, N] row-major;  TRANS_B=1 -> [N, K] row-major (C=A B^T)
//   Per-batch strides applied via blockIdx.z.
// Tile: BM=BN=128, BK=16, 256 threads, 8x8 per-thread microtile.
// ---------------------------------------------------------------------------
#define BM 128
#define BN 128
#define BK 16

template <bool TRANS_B, bool HAS_BIAS>
__global__ void __launch_bounds__(256, 2) sgemm_kernel(
    const float* __restrict__ A,
    const float* __restrict__ Bm,
    const float* __restrict__ bias,
    float scale,
    float* __restrict__ C,
    int M, int N, int K,
    size_t strideA, size_t strideB, size_t strideC)
{
    const int b = blockIdx.z;
    A  += (size_t)b * strideA;
    Bm += (size_t)b * strideB;
    C  += (size_t)b * strideC;

    __shared__ float As[BK][BM];   // transposed: As[k][m]
    __shared__ float Bs[BK][BN];   // Bs[k][n]

    const int tid = threadIdx.x;
    const int tx  = tid & 15;      // 0..15, column group
    const int ty  = tid >> 4;      // 0..15, row group
    const int row0 = blockIdx.y * BM;
    const int col0 = blockIdx.x * BN;

    float acc[8][8];
#pragma unroll
    for (int i = 0; i < 8; i++)
#pragma unroll
        for (int j = 0; j < 8; j++) acc[i][j] = 0.f;

    const int ra = tid >> 2;       // 0..63
    const int va = tid & 3;        // 0..3 (float4 index within a 16-wide k row)
    const int rb = tid >> 5;       // 0..7
    const int vb = tid & 31;       // 0..31

    for (int k0 = 0; k0 < K; k0 += BK) {
        // ---- load A tile (128 x 16), store transposed into As[k][m] ----
#pragma unroll
        for (int p = 0; p < 2; p++) {
            const int m = ra + p * 64;
            const float4 t = *(const float4*)&A[(size_t)(row0 + m) * K + k0 + va * 4];
            As[va * 4 + 0][m] = t.x;
            As[va * 4 + 1][m] = t.y;
            As[va * 4 + 2][m] = t.z;
            As[va * 4 + 3][m] = t.w;
        }
        // ---- load B tile into Bs[k][n] ----
        if (!TRANS_B) {
            // B: [K, N] row-major, coalesced along n
#pragma unroll
            for (int p = 0; p < 2; p++) {
                const int kk = rb + p * 8;
                *(float4*)&Bs[kk][vb * 4] =
                    *(const float4*)&Bm[(size_t)(k0 + kk) * N + col0 + vb * 4];
            }
        } else {
            // B: [N, K] row-major; load along k (coalesced), transpose into Bs
#pragma unroll
            for (int p = 0; p < 2; p++) {
                const int n = ra + p * 64;
                const float4 t = *(const float4*)&Bm[(size_t)(col0 + n) * K + k0 + va * 4];
                Bs[va * 4 + 0][n] = t.x;
                Bs[va * 4 + 1][n] = t.y;
                Bs[va * 4 + 2][n] = t.z;
                Bs[va * 4 + 3][n] = t.w;
            }
        }
        __syncthreads();

        // ---- compute ----
#pragma unroll
        for (int kk = 0; kk < BK; kk++) {
            float a[8], bb[8];
            const float4 a0 = *(const float4*)&As[kk][ty * 4];
            const float4 a1 = *(const float4*)&As[kk][64 + ty * 4];
            a[0]=a0.x; a[1]=a0.y; a[2]=a0.z; a[3]=a0.w;
            a[4]=a1.x; a[5]=a1.y; a[6]=a1.z; a[7]=a1.w;
            const float4 b0 = *(const float4*)&Bs[kk][tx * 4];
            const float4 b1 = *(const float4*)&Bs[kk][64 + tx * 4];
            bb[0]=b0.x; bb[1]=b0.y; bb[2]=b0.z; bb[3]=b0.w;
            bb[4]=b1.x; bb[5]=b1.y; bb[6]=b1.z; bb[7]=b1.w;
#pragma unroll
            for (int i = 0; i < 8; i++)
#pragma unroll
                for (int j = 0; j < 8; j++)
                    acc[i][j] = fmaf(a[i], bb[j], acc[i][j]);
        }
        __syncthreads();
    }

    // ---- epilogue: scale (+bias), float4 stores ----
#pragma unroll
    for (int i = 0; i < 8; i++) {
        const int m = row0 + ((i < 4) ? (ty * 4 + i) : (64 + ty * 4 + (i - 4)));
#pragma unroll
        for (int jb = 0; jb < 2; jb++) {
            const int n = col0 + jb * 64 + tx * 4;
            float4 o;
            o.x = acc[i][jb * 4 + 0] * scale;
            o.y = acc[i][jb * 4 + 1] * scale;
            o.z = acc[i][jb * 4 + 2] * scale;
            o.w = acc[i][jb * 4 + 3] * scale;
            if (HAS_BIAS) {
                o.x += bias[n + 0];
                o.y += bias[n + 1];
                o.z += bias[n + 2];
                o.w += bias[n + 3];
            }
            *(float4*)&C[(size_t)m * N + n] = o;
        }
    }
}

// ---------------------------------------------------------------------------
// Row softmax over S rows of length 4096. One block (256 threads) per row.
// Each thread holds its 16 values in registers: single read, single write.
// ---------------------------------------------------------------------------
__global__ void __launch_bounds__(256) softmax_rows_4096(float* __restrict__ S)
{
    float4* p = (float4*)(S + (size_t)blockIdx.x * SEQ);
    const int tid = threadIdx.x;

    float4 v[4];
    float mx = -3.4e38f;
#pragma unroll
    for (int i = 0; i < 4; i++) {
        v[i] = p[tid + i * 256];
        mx = fmaxf(mx, fmaxf(fmaxf(v[i].x, v[i].y), fmaxf(v[i].z, v[i].w)));
    }
    // block max
    __shared__ float red[8];
#pragma unroll
    for (int o = 16; o > 0; o >>= 1) mx = fmaxf(mx, __shfl_xor_sync(0xffffffffu, mx, o));
    if ((tid & 31) == 0) red[tid >> 5] = mx;
    __syncthreads();
    float bmx = red[0];
#pragma unroll
    for (int w = 1; w < 8; w++) bmx = fmaxf(bmx, red[w]);
    __syncthreads();

    float s = 0.f;
#pragma unroll
    for (int i = 0; i < 4; i++) {
        v[i].x = __expf(v[i].x - bmx);
        v[i].y = __expf(v[i].y - bmx);
        v[i].z = __expf(v[i].z - bmx);
        v[i].w = __expf(v[i].w - bmx);
        s += v[i].x + v[i].y + v[i].z + v[i].w;
    }
#pragma unroll
    for (int o = 16; o > 0; o >>= 1) s += __shfl_xor_sync(0xffffffffu, s, o);
    if ((tid & 31) == 0) red[tid >> 5] = s;
    __syncthreads();
    float bs = 0.f;
#pragma unroll
    for (int w = 0; w < 8; w++) bs += red[w];
    const float inv = __frcp_rn(bs);

#pragma unroll
    for (int i = 0; i < 4; i++) {
        v[i].x *= inv; v[i].y *= inv; v[i].z *= inv; v[i].w *= inv;
        p[tid + i * 256] = v[i];
    }
}

// ---------------------------------------------------------------------------
// kernel_launch
// ---------------------------------------------------------------------------
extern "C" void kernel_launch(void* const* d_in, const int* in_sizes, int n_in,
                              void* d_out, int out_size)
{
    const float* X  = (const float*)d_in[0];
    const float* Wq = (const float*)d_in[1];
    const float* Wk = (const float*)d_in[2];
    const float* Wv = (const float*)d_in[3];
    const float* bq = (const float*)d_in[4];
    const float* bk = (const float*)d_in[5];
    const float* bv = (const float*)d_in[6];
    float* out = (float*)d_out;

    float *Q, *K, *V, *S;
    cudaGetSymbolAddress((void**)&Q, g_Q);
    cudaGetSymbolAddress((void**)&K, g_K);
    cudaGetSymbolAddress((void**)&V, g_V);
    cudaGetSymbolAddress((void**)&S, g_S);

    const float scale = 0.03125f;  // 1/sqrt(1024)

    // 1) QKV projections: [16384,1024] = X[16384,1024] @ W[1024,1024] + b
    {
        dim3 grid(DIM / BN, MTOT / BM, 1);
        sgemm_kernel<false, true><<<grid, 256>>>(X, Wq, bq, 1.0f, Q,
                                                 MTOT, DIM, DIM, 0, 0, 0);
        sgemm_kernel<false, true><<<grid, 256>>>(X, Wk, bk, 1.0f, K,
                                                 MTOT, DIM, DIM, 0, 0, 0);
        sgemm_kernel<false, true><<<grid, 256>>>(X, Wv, bv, 1.0f, V,
                                                 MTOT, DIM, DIM, 0, 0, 0);
    }

    // 2) Scores: per batch, S[4096,4096] = (Q @ K^T) * 1/32
    {
        dim3 grid(SEQ / BN, SEQ / BM, B_BATCH);
        sgemm_kernel<true, false><<<grid, 256>>>(Q, K, nullptr, scale, S,
                                                 SEQ, SEQ, DIM,
                                                 (size_t)SEQ * DIM,
                                                 (size_t)SEQ * DIM,
                                                 (size_t)SEQ * SEQ);
    }

    // 3) Row softmax, in place
    softmax_rows_4096<<<B_BATCH * SEQ, 256>>>(S);

    // 4) Output: per batch, out[4096,1024] = P[4096,4096] @ V[4096,1024]
    {
        dim3 grid(DIM / BN, SEQ / BM, B_BATCH);
        sgemm_kernel<false, false><<<grid, 256>>>(S, V, nullptr, 1.0f, out,
                                                  SEQ, DIM, SEQ,
                                                  (size_t)SEQ * SEQ,
                                                  (size_t)SEQ * DIM,
                                                  (size_t)SEQ * DIM);
    }
}

// round 3
// speedup vs baseline: 1.9443x; 1.9443x over previous
#include <cuda_runtime.h>
#include <cuda_bf16.h>
#include <cstdint>

// Shapes fixed by dataset:
//   X [4,4096,1024] f32 ; Wq/Wk/Wv [1024,1024] ; bq/bk/bv [1024]
//   out[4,4096,1024] = softmax((XWq+bq)(XWk+bk)^T / 32) (XWv+bv)

#define SEQ   4096
#define DIM   1024
#define NB    4
#define MTOT  (NB*SEQ)          // 16384

typedef __nv_bfloat16 bf16;

// ---------------------------------------------------------------------------
// Device scratch (no allocation allowed)
// ---------------------------------------------------------------------------
__device__ __align__(256) bf16 g_Xh[(size_t)MTOT*DIM], g_Xl[(size_t)MTOT*DIM];
__device__ __align__(256) bf16 g_Wqh[DIM*DIM], g_Wql[DIM*DIM];
__device__ __align__(256) bf16 g_Wkh[DIM*DIM], g_Wkl[DIM*DIM];
__device__ __align__(256) bf16 g_Wvh[DIM*DIM], g_Wvl[DIM*DIM];
__device__ __align__(256) bf16 g_Qh[(size_t)MTOT*DIM], g_Ql[(size_t)MTOT*DIM];
__device__ __align__(256) bf16 g_Kh[(size_t)MTOT*DIM], g_Kl[(size_t)MTOT*DIM];
__device__ __align__(256) bf16 g_Vth[(size_t)DIM*MTOT], g_Vtl[(size_t)DIM*MTOT]; // V^T [dim, tokens]
__device__ __align__(256) float g_S [(size_t)NB*SEQ*SEQ];
__device__ __align__(256) bf16 g_Ph[(size_t)NB*SEQ*SEQ], g_Pl[(size_t)NB*SEQ*SEQ];

// ---------------------------------------------------------------------------
// Plain-PTX helpers (sm_80+ features only: cp.async / ldmatrix / mma.sync)
// ---------------------------------------------------------------------------
__device__ __forceinline__ uint32_t smem_u32(const void* p) {
    uint32_t a;
    asm("{ .reg .u64 t; cvta.to.shared.u64 t, %1; cvt.u32.u64 %0, t; }" : "=r"(a) : "l"(p));
    return a;
}
__device__ __forceinline__ void cp16(uint32_t dst, const void* src) {
    asm volatile("cp.async.cg.shared.global [%0], [%1], 16;" :: "r"(dst), "l"(src) : "memory");
}
#define CP_COMMIT() asm volatile("cp.async.commit_group;" ::: "memory")
#define CP_WAIT(n)  asm volatile("cp.async.wait_group %0;" :: "n"(n) : "memory")

__device__ __forceinline__ void ldsm4(uint32_t* r, uint32_t addr) {
    asm volatile("ldmatrix.sync.aligned.m8n8.x4.shared.b16 {%0,%1,%2,%3}, [%4];"
                 : "=r"(r[0]), "=r"(r[1]), "=r"(r[2]), "=r"(r[3]) : "r"(addr));
}
__device__ __forceinline__ void mma16816(float* d, const uint32_t* a, uint32_t b0, uint32_t b1) {
    asm volatile(
        "mma.sync.aligned.m16n8k16.row.col.f32.bf16.bf16.f32 "
        "{%0,%1,%2,%3}, {%4,%5,%6,%7}, {%8,%9}, {%0,%1,%2,%3};"
        : "+f"(d[0]), "+f"(d[1]), "+f"(d[2]), "+f"(d[3])
        : "r"(a[0]), "r"(a[1]), "r"(a[2]), "r"(a[3]), "r"(b0), "r"(b1));
}
__device__ __forceinline__ void split2(float f, bf16& h, bf16& l) {
    h = __float2bfloat16_rn(f);
    l = __float2bfloat16_rn(f - __bfloat162float(h));
}

// ---------------------------------------------------------------------------
// GEMM: C[M,N] = scale*(A B^T) (+bias), A=[M,K] and B=[N,K] both as bf16
// hi/lo pairs. 3 K-segments: Ah*Bh, Al*Bh, Ah*Bl (2-term split => ~fp32).
// Tile 128x128x32, 256 threads (2x4 warps, 64x32 warp tile), 4-stage cp.async.
// ---------------------------------------------------------------------------
#define BM 128
#define BN 128
#define BK 32
#define STAGES 4
#define ROWB 80                        // padded smem row: 32 bf16 (64B) -> 80B
#define ATILE_B (128*ROWB)             // 10240
#define STAGE_B (2*ATILE_B)            // 20480 (A + B)
#define SMEM_TOTAL (STAGES*STAGE_B)    // 81920

enum { EPI_PAIR_BIASN = 0, EPI_PAIR_BIASM = 1, EPI_F32_SCALE = 2, EPI_F32 = 3 };

__device__ __forceinline__ void load_stage(uint32_t sm, const bf16* pA, int lda,
                                           const bf16* pB, int ldb, int koff, int tid) {
#pragma unroll
    for (int rep = 0; rep < 2; rep++) {
        const int idx = tid + rep * 256;
        const int row = idx >> 2, j = idx & 3;
        cp16(sm + row * ROWB + j * 16, pA + (size_t)row * lda + koff + j * 8);
        cp16(sm + ATILE_B + row * ROWB + j * 16, pB + (size_t)row * ldb + koff + j * 8);
    }
}

template <int MODE>
__global__ void __launch_bounds__(256)
mma_gemm(const bf16* __restrict__ Ah, const bf16* __restrict__ Al,
         int lda, unsigned long long strA,
         const bf16* __restrict__ Bh, const bf16* __restrict__ Bl,
         int ldb, unsigned long long strB,
         const float* __restrict__ bias, float scale,
         float* __restrict__ Cf, bf16* __restrict__ Ch, bf16* __restrict__ Cl,
         int ldc, unsigned long long strC, int K, int scLog)
{
    extern __shared__ __align__(256) char smem[];
    const uint32_t sbase = smem_u32(smem);
    const int tid = threadIdx.x;
    const int wid = tid >> 5, lane = tid & 31;
    const int warpM = wid >> 2, warpN = wid & 3;      // 2 x 4 warp grid
    const int z = blockIdx.z;
    const int col0 = blockIdx.x * BN, row0 = blockIdx.y * BM;

    const bf16* Ah_ = Ah + (size_t)z * strA + (size_t)row0 * lda;
    const bf16* Al_ = Al + (size_t)z * strA + (size_t)row0 * lda;
    const bf16* Bh_ = Bh + (size_t)z * strB + (size_t)col0 * ldb;
    const bf16* Bl_ = Bl + (size_t)z * strB + (size_t)col0 * ldb;

    const int segC = 1 << scLog;        // chunks per segment = K/32
    const int NC = 3 * segC;

    float d[4][4][4];
#pragma unroll
    for (int i = 0; i < 4; i++)
#pragma unroll
        for (int j = 0; j < 4; j++)
#pragma unroll
            for (int e = 0; e < 4; e++) d[i][j][e] = 0.f;

    // prologue: stages 0..STAGES-2
#pragma unroll
    for (int s = 0; s < STAGES - 1; s++) {
        const int seg = s >> scLog;
        const int koff = (s & (segC - 1)) << 5;
        const bf16* pA = (seg == 1) ? Al_ : Ah_;
        const bf16* pB = (seg == 2) ? Bl_ : Bh_;
        load_stage(sbase + s * STAGE_B, pA, lda, pB, ldb, koff, tid);
        CP_COMMIT();
    }

    // ldmatrix base addresses (per lane), fixed row/col components
    const int lrow = lane & 15;          // row within 16-row tile
    const int lcolh = lane >> 4;         // k half (0/1)

    for (int c = 0; c < NC; c++) {
        CP_WAIT(STAGES - 2);
        __syncthreads();

        // issue next stage loads into the slot freed at iter c-1
        const int cn = c + STAGES - 1;
        if (cn < NC) {
            const int seg = cn >> scLog;
            const int koff = (cn & (segC - 1)) << 5;
            const bf16* pA = (seg == 1) ? Al_ : Ah_;
            const bf16* pB = (seg == 2) ? Bl_ : Bh_;
            load_stage(sbase + (cn % STAGES) * STAGE_B, pA, lda, pB, ldb, koff, tid);
        }
        CP_COMMIT();

        const uint32_t As = sbase + (c % STAGES) * STAGE_B;
        const uint32_t Bs = As + ATILE_B;

#pragma unroll
        for (int ks = 0; ks < 2; ks++) {
            const int c16 = ks * 2 + lcolh;   // 16B chunk index within row
            uint32_t a[4][4];
#pragma unroll
            for (int i = 0; i < 4; i++) {
                const int r = warpM * 64 + i * 16 + lrow;
                ldsm4(a[i], As + r * ROWB + c16 * 16);
            }
            uint32_t bfr[2][4];
#pragma unroll
            for (int p = 0; p < 2; p++) {
                const int r = warpN * 32 + p * 16 + lrow;
                ldsm4(bfr[p], Bs + r * ROWB + c16 * 16);
            }
            // bfr[p] = {n(2p) k0, n(2p+1) k0, n(2p) k1, n(2p+1) k1}
#pragma unroll
            for (int i = 0; i < 4; i++)
#pragma unroll
                for (int j = 0; j < 4; j++) {
                    const int p = j >> 1, s = j & 1;
                    mma16816(d[i][j], a[i], bfr[p][s], bfr[p][s + 2]);
                }
        }
    }

    // ------------------------- epilogue -------------------------
    const int qr = lane >> 2;            // 0..7
    const int qc = (lane & 3) * 2;       // 0,2,4,6
#pragma unroll
    for (int i = 0; i < 4; i++) {
#pragma unroll
        for (int j = 0; j < 4; j++) {
            const int r = row0 + warpM * 64 + i * 16 + qr;
            const int ccol = col0 + warpN * 32 + j * 8 + qc;
#pragma unroll
            for (int h = 0; h < 2; h++) {            // h=0: rows r, h=1: r+8
                const int rr = r + h * 8;
                float f0 = d[i][j][h * 2 + 0];
                float f1 = d[i][j][h * 2 + 1];
                if (MODE == EPI_F32_SCALE || MODE == EPI_F32) {
                    float2 o; o.x = f0 * scale; o.y = f1 * scale;
                    *(float2*)(Cf + (size_t)z * strC + (size_t)rr * ldc + ccol) = o;
                } else {
                    if (MODE == EPI_PAIR_BIASN) { f0 += bias[ccol]; f1 += bias[ccol + 1]; }
                    else                        { f0 += bias[rr];   f1 += bias[rr]; }
                    bf16 h0, l0, h1, l1;
                    split2(f0, h0, l0); split2(f1, h1, l1);
                    __nv_bfloat162 hp; hp.x = h0; hp.y = h1;
                    __nv_bfloat162 lp; lp.x = l0; lp.y = l1;
                    const size_t off = (size_t)z * strC + (size_t)rr * ldc + ccol;
                    *(__nv_bfloat162*)(Ch + off) = hp;
                    *(__nv_bfloat162*)(Cl + off) = lp;
                }
            }
        }
    }
}

// ---------------------------------------------------------------------------
// f32 -> bf16 hi/lo split (vectorized)
// ---------------------------------------------------------------------------
__global__ void __launch_bounds__(256) split_pair4(const float4* __restrict__ x,
                                                   bf16* __restrict__ h, bf16* __restrict__ l)
{
    const size_t i = (size_t)blockIdx.x * 256 + threadIdx.x;
    const float4 v = x[i];
    bf16 h0, l0, h1, l1, h2, l2, h3, l3;
    split2(v.x, h0, l0); split2(v.y, h1, l1); split2(v.z, h2, l2); split2(v.w, h3, l3);
    __nv_bfloat162 ha; ha.x = h0; ha.y = h1;
    __nv_bfloat162 hb; hb.x = h2; hb.y = h3;
    __nv_bfloat162 la; la.x = l0; la.y = l1;
    __nv_bfloat162 lb; lb.x = l2; lb.y = l3;
    ((uint2*)h)[i] = make_uint2(*(uint32_t*)&ha, *(uint32_t*)&hb);
    ((uint2*)l)[i] = make_uint2(*(uint32_t*)&la, *(uint32_t*)&lb);
}

// W [K=1024, N=1024] row-major -> transposed split Th/Tl [N,K]
__global__ void __launch_bounds__(256) splitT1024(const float* __restrict__ W,
                                                  bf16* __restrict__ Th, bf16* __restrict__ Tl)
{
    const int idx = blockIdx.x * 256 + threadIdx.x;
    const int k = idx >> 10, n = idx & 1023;
    bf16 h, l; split2(W[idx], h, l);
    Th[n * 1024 + k] = h;
    Tl[n * 1024 + k] = l;
}

// ---------------------------------------------------------------------------
// Row softmax (len 4096) -> bf16 hi/lo pair
// ---------------------------------------------------------------------------
__global__ void __launch_bounds__(256) softmax_split(const float* __restrict__ S,
                                                     bf16* __restrict__ Ph, bf16* __restrict__ Pl)
{
    const float4* p = (const float4*)(S + (size_t)blockIdx.x * SEQ);
    const int tid = threadIdx.x;

    float4 v[4];
    float mx = -3.4e38f;
#pragma unroll
    for (int i = 0; i < 4; i++) {
        v[i] = p[tid + i * 256];
        mx = fmaxf(mx, fmaxf(fmaxf(v[i].x, v[i].y), fmaxf(v[i].z, v[i].w)));
    }
    __shared__ float red[8];
#pragma unroll
    for (int o = 16; o > 0; o >>= 1) mx = fmaxf(mx, __shfl_xor_sync(0xffffffffu, mx, o));
    if ((tid & 31) == 0) red[tid >> 5] = mx;
    __syncthreads();
    float bmx = red[0];
#pragma unroll
    for (int w = 1; w < 8; w++) bmx = fmaxf(bmx, red[w]);
    __syncthreads();

    float s = 0.f;
#pragma unroll
    for (int i = 0; i < 4; i++) {
        v[i].x = __expf(v[i].x - bmx);
        v[i].y = __expf(v[i].y - bmx);
        v[i].z = __expf(v[i].z - bmx);
        v[i].w = __expf(v[i].w - bmx);
        s += v[i].x + v[i].y + v[i].z + v[i].w;
    }
#pragma unroll
    for (int o = 16; o > 0; o >>= 1) s += __shfl_xor_sync(0xffffffffu, s, o);
    if ((tid & 31) == 0) red[tid >> 5] = s;
    __syncthreads();
    float bs = 0.f;
#pragma unroll
    for (int w = 0; w < 8; w++) bs += red[w];
    const float inv = __frcp_rn(bs);

    uint2* oh = (uint2*)(Ph + (size_t)blockIdx.x * SEQ);
    uint2* ol = (uint2*)(Pl + (size_t)blockIdx.x * SEQ);
#pragma unroll
    for (int i = 0; i < 4; i++) {
        const float f0 = v[i].x * inv, f1 = v[i].y * inv, f2 = v[i].z * inv, f3 = v[i].w * inv;
        bf16 h0, l0, h1, l1, h2, l2, h3, l3;
        split2(f0, h0, l0); split2(f1, h1, l1); split2(f2, h2, l2); split2(f3, h3, l3);
        __nv_bfloat162 ha; ha.x = h0; ha.y = h1;
        __nv_bfloat162 hb; hb.x = h2; hb.y = h3;
        __nv_bfloat162 la; la.x = l0; la.y = l1;
        __nv_bfloat162 lb; lb.x = l2; lb.y = l3;
        oh[tid + i * 256] = make_uint2(*(uint32_t*)&ha, *(uint32_t*)&hb);
        ol[tid + i * 256] = make_uint2(*(uint32_t*)&la, *(uint32_t*)&lb);
    }
}

// ---------------------------------------------------------------------------
// kernel_launch
// ---------------------------------------------------------------------------
extern "C" void kernel_launch(void* const* d_in, const int* in_sizes, int n_in,
                              void* d_out, int out_size)
{
    const float* X  = (const float*)d_in[0];
    const float* Wq = (const float*)d_in[1];
    const float* Wk = (const float*)d_in[2];
    const float* Wv = (const float*)d_in[3];
    const float* bq = (const float*)d_in[4];
    const float* bk = (const float*)d_in[5];
    const float* bv = (const float*)d_in[6];
    float* out = (float*)d_out;

    static bool attr_done = false;
    if (!attr_done) {
        cudaFuncSetAttribute(mma_gemm<EPI_PAIR_BIASN>, cudaFuncAttributeMaxDynamicSharedMemorySize, SMEM_TOTAL);
        cudaFuncSetAttribute(mma_gemm<EPI_PAIR_BIASM>, cudaFuncAttributeMaxDynamicSharedMemorySize, SMEM_TOTAL);
        cudaFuncSetAttribute(mma_gemm<EPI_F32_SCALE>,  cudaFuncAttributeMaxDynamicSharedMemorySize, SMEM_TOTAL);
        cudaFuncSetAttribute(mma_gemm<EPI_F32>,        cudaFuncAttributeMaxDynamicSharedMemorySize, SMEM_TOTAL);
        attr_done = true;
    }

    bf16 *Xh, *Xl, *Wqh, *Wql, *Wkh, *Wkl, *Wvh, *Wvl;
    bf16 *Qh, *Ql, *Kh, *Kl, *Vth, *Vtl, *Ph, *Pl;
    float* S;
    cudaGetSymbolAddress((void**)&Xh,  g_Xh);  cudaGetSymbolAddress((void**)&Xl,  g_Xl);
    cudaGetSymbolAddress((void**)&Wqh, g_Wqh); cudaGetSymbolAddress((void**)&Wql, g_Wql);
    cudaGetSymbolAddress((void**)&Wkh, g_Wkh); cudaGetSymbolAddress((void**)&Wkl, g_Wkl);
    cudaGetSymbolAddress((void**)&Wvh, g_Wvh); cudaGetSymbolAddress((void**)&Wvl, g_Wvl);
    cudaGetSymbolAddress((void**)&Qh,  g_Qh);  cudaGetSymbolAddress((void**)&Ql,  g_Ql);
    cudaGetSymbolAddress((void**)&Kh,  g_Kh);  cudaGetSymbolAddress((void**)&Kl,  g_Kl);
    cudaGetSymbolAddress((void**)&Vth, g_Vth); cudaGetSymbolAddress((void**)&Vtl, g_Vtl);
    cudaGetSymbolAddress((void**)&Ph,  g_Ph);  cudaGetSymbolAddress((void**)&Pl,  g_Pl);
    cudaGetSymbolAddress((void**)&S,   g_S);

    // 0) splits
    split_pair4<<<MTOT * DIM / 1024, 256>>>((const float4*)X, Xh, Xl);
    splitT1024<<<DIM * DIM / 256, 256>>>(Wq, Wqh, Wql);
    splitT1024<<<DIM * DIM / 256, 256>>>(Wk, Wkh, Wkl);
    splitT1024<<<DIM * DIM / 256, 256>>>(Wv, Wvh, Wvl);

    // 1) Q = X Wq + bq ; K = X Wk + bk  (bf16-pair outputs)
    mma_gemm<EPI_PAIR_BIASN><<<dim3(DIM / BN, MTOT / BM, 1), 256, SMEM_TOTAL>>>(
        Xh, Xl, DIM, 0, Wqh, Wql, DIM, 0, bq, 1.f,
        nullptr, Qh, Ql, DIM, 0, DIM, 5);
    mma_gemm<EPI_PAIR_BIASN><<<dim3(DIM / BN, MTOT / BM, 1), 256, SMEM_TOTAL>>>(
        Xh, Xl, DIM, 0, Wkh, Wkl, DIM, 0, bk, 1.f,
        nullptr, Kh, Kl, DIM, 0, DIM, 5);
    //    Vt = Wv^T X^T + bv (bias along M); Vt [dim, tokens]
    mma_gemm<EPI_PAIR_BIASM><<<dim3(MTOT / BN, DIM / BM, 1), 256, SMEM_TOTAL>>>(
        Wvh, Wvl, DIM, 0, Xh, Xl, DIM, 0, bv, 1.f,
        nullptr, Vth, Vtl, MTOT, 0, DIM, 5);

    // 2) S = (Q K^T) / 32 per batch
    mma_gemm<EPI_F32_SCALE><<<dim3(SEQ / BN, SEQ / BM, NB), 256, SMEM_TOTAL>>>(
        Qh, Ql, DIM, (unsigned long long)SEQ * DIM,
        Kh, Kl, DIM, (unsigned long long)SEQ * DIM,
        nullptr, 0.03125f,
        S, nullptr, nullptr, SEQ, (unsigned long long)SEQ * SEQ, DIM, 5);

    // 3) softmax rows -> P pair
    softmax_split<<<NB * SEQ, 256>>>(S, Ph, Pl);

    // 4) out = P V per batch (B operand = Vt, batch selects column block)
    mma_gemm<EPI_F32><<<dim3(DIM / BN, SEQ / BM, NB), 256, SMEM_TOTAL>>>(
        Ph, Pl, SEQ, (unsigned long long)SEQ * SEQ,
        Vth, Vtl, MTOT, (unsigned long long)SEQ,
        nullptr, 1.f,
        out, nullptr, nullptr, DIM, (unsigned long long)SEQ * DIM, SEQ, 7);
}

// round 4
// speedup vs baseline: 3.5872x; 1.8450x over previous
#include <cuda_runtime.h>
#include <cuda_bf16.h>
#include <cuda_fp16.h>
#include <cstdint>

// Shapes fixed by dataset:
//   X [4,4096,1024] f32 ; Wq/Wk/Wv [1024,1024] ; bq/bk/bv [1024]
//   out[4,4096,1024] = softmax((XWq+bq)(XWk+bk)^T / 32) (XWv+bv)

#define SEQ   4096
#define DIM   1024
#define NB    4
#define MTOT  (NB*SEQ)          // 16384

typedef __nv_bfloat16 bf16;
typedef __half fp16;

// ---------------------------------------------------------------------------
// Device scratch (no allocation allowed)
// ---------------------------------------------------------------------------
__device__ __align__(256) bf16 g_Xh[(size_t)MTOT*DIM], g_Xl[(size_t)MTOT*DIM];
__device__ __align__(256) bf16 g_Wqh[DIM*DIM], g_Wql[DIM*DIM];
__device__ __align__(256) bf16 g_Wkh[DIM*DIM], g_Wkl[DIM*DIM];
__device__ __align__(256) bf16 g_Wvh[DIM*DIM], g_Wvl[DIM*DIM];
__device__ __align__(256) fp16 g_Q [(size_t)MTOT*DIM];
__device__ __align__(256) fp16 g_K [(size_t)MTOT*DIM];
__device__ __align__(256) fp16 g_Vt[(size_t)DIM*MTOT];          // V^T [dim, tokens]
__device__ __align__(256) float g_S [(size_t)NB*SEQ*SEQ];
__device__ __align__(256) fp16 g_P [(size_t)NB*SEQ*SEQ];

// ---------------------------------------------------------------------------
// sm_80-class PTX helpers (cp.async / ldmatrix / mma.sync)
// ---------------------------------------------------------------------------
__device__ __forceinline__ uint32_t smem_u32(const void* p) {
    uint32_t a;
    asm("{ .reg .u64 t; cvta.to.shared.u64 t, %1; cvt.u32.u64 %0, t; }" : "=r"(a) : "l"(p));
    return a;
}
__device__ __forceinline__ void cp16(uint32_t dst, const void* src) {
    asm volatile("cp.async.cg.shared.global [%0], [%1], 16;" :: "r"(dst), "l"(src) : "memory");
}
#define CP_COMMIT() asm volatile("cp.async.commit_group;" ::: "memory")
#define CP_WAIT(n)  asm volatile("cp.async.wait_group %0;" :: "n"(n) : "memory")

__device__ __forceinline__ void ldsm4(uint32_t* r, uint32_t addr) {
    asm volatile("ldmatrix.sync.aligned.m8n8.x4.shared.b16 {%0,%1,%2,%3}, [%4];"
                 : "=r"(r[0]), "=r"(r[1]), "=r"(r[2]), "=r"(r[3]) : "r"(addr));
}
template <typename T>
__device__ __forceinline__ void mma16816(float* d, const uint32_t* a, uint32_t b0, uint32_t b1);
template <>
__device__ __forceinline__ void mma16816<bf16>(float* d, const uint32_t* a, uint32_t b0, uint32_t b1) {
    asm volatile(
        "mma.sync.aligned.m16n8k16.row.col.f32.bf16.bf16.f32 "
        "{%0,%1,%2,%3}, {%4,%5,%6,%7}, {%8,%9}, {%0,%1,%2,%3};"
        : "+f"(d[0]), "+f"(d[1]), "+f"(d[2]), "+f"(d[3])
        : "r"(a[0]), "r"(a[1]), "r"(a[2]), "r"(a[3]), "r"(b0), "r"(b1));
}
template <>
__device__ __forceinline__ void mma16816<fp16>(float* d, const uint32_t* a, uint32_t b0, uint32_t b1) {
    asm volatile(
        "mma.sync.aligned.m16n8k16.row.col.f32.f16.f16.f32 "
        "{%0,%1,%2,%3}, {%4,%5,%6,%7}, {%8,%9}, {%0,%1,%2,%3};"
        : "+f"(d[0]), "+f"(d[1]), "+f"(d[2]), "+f"(d[3])
        : "r"(a[0]), "r"(a[1]), "r"(a[2]), "r"(a[3]), "r"(b0), "r"(b1));
}
__device__ __forceinline__ void split2(float f, bf16& h, bf16& l) {
    h = __float2bfloat16_rn(f);
    l = __float2bfloat16_rn(f - __bfloat162float(h));
}

// ---------------------------------------------------------------------------
// GEMM: C[M,N] = scale*(A B^T) (+bias). NPASS=3: A,B are hi/lo pairs, passes
// AhBh + AlBh + AhBl (2-term split => ~fp32). NPASS=1: single operands.
// Tile 128x128x32, 256 threads (2x4 warps, 64x32 warp tile), 4-stage cp.async.
// ---------------------------------------------------------------------------
#define BM 128
#define BN 128
#define BK 32
#define STAGES 4
#define ROWB 80                        // padded smem row: 32 elts (64B) -> 80B
#define ATILE_B (128*ROWB)             // 10240
#define STAGE_B (2*ATILE_B)            // 20480 (A + B)
#define SMEM_TOTAL (STAGES*STAGE_B)    // 81920

enum { EPI_H_BIASN = 0, EPI_H_BIASM = 1, EPI_F32_SCALE = 2, EPI_F32 = 3 };

template <typename T>
__device__ __forceinline__ void load_stage(uint32_t sm, const T* pA, int lda,
                                           const T* pB, int ldb, int koff, int tid) {
#pragma unroll
    for (int rep = 0; rep < 2; rep++) {
        const int idx = tid + rep * 256;
        const int row = idx >> 2, j = idx & 3;
        cp16(sm + row * ROWB + j * 16, pA + (size_t)row * lda + koff + j * 8);
        cp16(sm + ATILE_B + row * ROWB + j * 16, pB + (size_t)row * ldb + koff + j * 8);
    }
}

template <int MODE, typename T, int NPASS>
__global__ void __launch_bounds__(256)
mma_gemm(const T* __restrict__ Ah, const T* __restrict__ Al,
         int lda, unsigned long long strA,
         const T* __restrict__ Bh, const T* __restrict__ Bl,
         int ldb, unsigned long long strB,
         const float* __restrict__ bias, float scale,
         float* __restrict__ Cf, fp16* __restrict__ Ch,
         int ldc, unsigned long long strC, int scLog)
{
    extern __shared__ __align__(256) char smem[];
    const uint32_t sbase = smem_u32(smem);
    const int tid = threadIdx.x;
    const int wid = tid >> 5, lane = tid & 31;
    const int warpM = wid >> 2, warpN = wid & 3;      // 2 x 4 warp grid
    const int z = blockIdx.z;
    const int col0 = blockIdx.x * BN, row0 = blockIdx.y * BM;

    const T* Ah_ = Ah + (size_t)z * strA + (size_t)row0 * lda;
    const T* Al_ = (NPASS == 3) ? (Al + (size_t)z * strA + (size_t)row0 * lda) : Ah_;
    const T* Bh_ = Bh + (size_t)z * strB + (size_t)col0 * ldb;
    const T* Bl_ = (NPASS == 3) ? (Bl + (size_t)z * strB + (size_t)col0 * ldb) : Bh_;

    const int segC = 1 << scLog;        // chunks per pass = K/32
    const int NC = NPASS << scLog;

    float d[4][4][4];
#pragma unroll
    for (int i = 0; i < 4; i++)
#pragma unroll
        for (int j = 0; j < 4; j++)
#pragma unroll
            for (int e = 0; e < 4; e++) d[i][j][e] = 0.f;

    // prologue: stages 0..STAGES-2
#pragma unroll
    for (int s = 0; s < STAGES - 1; s++) {
        const int seg = (NPASS == 1) ? 0 : (s >> scLog);
        const int koff = (s & (segC - 1)) << 5;
        const T* pA = (seg == 1) ? Al_ : Ah_;
        const T* pB = (seg == 2) ? Bl_ : Bh_;
        load_stage(sbase + s * STAGE_B, pA, lda, pB, ldb, koff, tid);
        CP_COMMIT();
    }

    const int lrow = lane & 15;          // row within 16-row tile
    const int lcolh = lane >> 4;         // k half (0/1)

    for (int c = 0; c < NC; c++) {
        CP_WAIT(STAGES - 2);
        __syncthreads();

        const int cn = c + STAGES - 1;
        if (cn < NC) {
            const int seg = (NPASS == 1) ? 0 : (cn >> scLog);
            const int koff = (cn & (segC - 1)) << 5;
            const T* pA = (seg == 1) ? Al_ : Ah_;
            const T* pB = (seg == 2) ? Bl_ : Bh_;
            load_stage(sbase + (cn % STAGES) * STAGE_B, pA, lda, pB, ldb, koff, tid);
        }
        CP_COMMIT();

        const uint32_t As = sbase + (c % STAGES) * STAGE_B;
        const uint32_t Bs = As + ATILE_B;

#pragma unroll
        for (int ks = 0; ks < 2; ks++) {
            const int c16 = ks * 2 + lcolh;
            uint32_t a[4][4];
#pragma unroll
            for (int i = 0; i < 4; i++) {
                const int r = warpM * 64 + i * 16 + lrow;
                ldsm4(a[i], As + r * ROWB + c16 * 16);
            }
            uint32_t bfr[2][4];
#pragma unroll
            for (int p = 0; p < 2; p++) {
                const int r = warpN * 32 + p * 16 + lrow;
                ldsm4(bfr[p], Bs + r * ROWB + c16 * 16);
            }
#pragma unroll
            for (int i = 0; i < 4; i++)
#pragma unroll
                for (int j = 0; j < 4; j++) {
                    const int p = j >> 1, s = j & 1;
                    mma16816<T>(d[i][j], a[i], bfr[p][s], bfr[p][s + 2]);
                }
        }
    }

    // ------------------------- epilogue -------------------------
    const int qr = lane >> 2;            // 0..7
    const int qc = (lane & 3) * 2;       // 0,2,4,6
#pragma unroll
    for (int i = 0; i < 4; i++) {
#pragma unroll
        for (int j = 0; j < 4; j++) {
            const int r = row0 + warpM * 64 + i * 16 + qr;
            const int ccol = col0 + warpN * 32 + j * 8 + qc;
#pragma unroll
            for (int h = 0; h < 2; h++) {            // h=0: rows r, h=1: r+8
                const int rr = r + h * 8;
                float f0 = d[i][j][h * 2 + 0];
                float f1 = d[i][j][h * 2 + 1];
                if (MODE == EPI_F32_SCALE || MODE == EPI_F32) {
                    float2 o; o.x = f0 * scale; o.y = f1 * scale;
                    *(float2*)(Cf + (size_t)z * strC + (size_t)rr * ldc + ccol) = o;
                } else {
                    if (MODE == EPI_H_BIASN) { f0 += bias[ccol]; f1 += bias[ccol + 1]; }
                    else                     { f0 += bias[rr];   f1 += bias[rr]; }
                    const size_t off = (size_t)z * strC + (size_t)rr * ldc + ccol;
                    *(__half2*)(Ch + off) = __floats2half2_rn(f0, f1);
                }
            }
        }
    }
}

// ---------------------------------------------------------------------------
// f32 -> bf16 hi/lo split (vectorized)
// ---------------------------------------------------------------------------
__global__ void __launch_bounds__(256) split_pair4(const float4* __restrict__ x,
                                                   bf16* __restrict__ h, bf16* __restrict__ l)
{
    const size_t i = (size_t)blockIdx.x * 256 + threadIdx.x;
    const float4 v = x[i];
    bf16 h0, l0, h1, l1, h2, l2, h3, l3;
    split2(v.x, h0, l0); split2(v.y, h1, l1); split2(v.z, h2, l2); split2(v.w, h3, l3);
    __nv_bfloat162 ha; ha.x = h0; ha.y = h1;
    __nv_bfloat162 hb; hb.x = h2; hb.y = h3;
    __nv_bfloat162 la; la.x = l0; la.y = l1;
    __nv_bfloat162 lb; lb.x = l2; lb.y = l3;
    ((uint2*)h)[i] = make_uint2(*(uint32_t*)&ha, *(uint32_t*)&hb);
    ((uint2*)l)[i] = make_uint2(*(uint32_t*)&la, *(uint32_t*)&lb);
}

// W [K=1024, N=1024] row-major -> transposed split Th/Tl [N,K]
__global__ void __launch_bounds__(256) splitT1024(const float* __restrict__ W,
                                                  bf16* __restrict__ Th, bf16* __restrict__ Tl)
{
    const int idx = blockIdx.x * 256 + threadIdx.x;
    const int k = idx >> 10, n = idx & 1023;
    bf16 h, l; split2(W[idx], h, l);
    Th[n * 1024 + k] = h;
    Tl[n * 1024 + k] = l;
}

// ---------------------------------------------------------------------------
// Row softmax (len 4096) -> fp16 probabilities
// ---------------------------------------------------------------------------
__global__ void __launch_bounds__(256) softmax_h(const float* __restrict__ S,
                                                 fp16* __restrict__ P)
{
    const float4* p = (const float4*)(S + (size_t)blockIdx.x * SEQ);
    const int tid = threadIdx.x;

    float4 v[4];
    float mx = -3.4e38f;
#pragma unroll
    for (int i = 0; i < 4; i++) {
        v[i] = p[tid + i * 256];
        mx = fmaxf(mx, fmaxf(fmaxf(v[i].x, v[i].y), fmaxf(v[i].z, v[i].w)));
    }
    __shared__ float red[8];
#pragma unroll
    for (int o = 16; o > 0; o >>= 1) mx = fmaxf(mx, __shfl_xor_sync(0xffffffffu, mx, o));
    if ((tid & 31) == 0) red[tid >> 5] = mx;
    __syncthreads();
    float bmx = red[0];
#pragma unroll
    for (int w = 1; w < 8; w++) bmx = fmaxf(bmx, red[w]);
    __syncthreads();

    float s = 0.f;
#pragma unroll
    for (int i = 0; i < 4; i++) {
        v[i].x = __expf(v[i].x - bmx);
        v[i].y = __expf(v[i].y - bmx);
        v[i].z = __expf(v[i].z - bmx);
        v[i].w = __expf(v[i].w - bmx);
        s += v[i].x + v[i].y + v[i].z + v[i].w;
    }
#pragma unroll
    for (int o = 16; o > 0; o >>= 1) s += __shfl_xor_sync(0xffffffffu, s, o);
    if ((tid & 31) == 0) red[tid >> 5] = s;
    __syncthreads();
    float bs = 0.f;
#pragma unroll
    for (int w = 0; w < 8; w++) bs += red[w];
    const float inv = __frcp_rn(bs);

    uint2* op = (uint2*)(P + (size_t)blockIdx.x * SEQ);
#pragma unroll
    for (int i = 0; i < 4; i++) {
        __half2 a = __floats2half2_rn(v[i].x * inv, v[i].y * inv);
        __half2 b = __floats2half2_rn(v[i].z * inv, v[i].w * inv);
        op[tid + i * 256] = make_uint2(*(uint32_t*)&a, *(uint32_t*)&b);
    }
}

// ---------------------------------------------------------------------------
// kernel_launch
// ---------------------------------------------------------------------------
extern "C" void kernel_launch(void* const* d_in, const int* in_sizes, int n_in,
                              void* d_out, int out_size)
{
    const float* X  = (const float*)d_in[0];
    const float* Wq = (const float*)d_in[1];
    const float* Wk = (const float*)d_in[2];
    const float* Wv = (const float*)d_in[3];
    const float* bq = (const float*)d_in[4];
    const float* bk = (const float*)d_in[5];
    const float* bv = (const float*)d_in[6];
    float* out = (float*)d_out;

    static bool attr_done = false;
    if (!attr_done) {
        cudaFuncSetAttribute(mma_gemm<EPI_H_BIASN, bf16, 3>,  cudaFuncAttributeMaxDynamicSharedMemorySize, SMEM_TOTAL);
        cudaFuncSetAttribute(mma_gemm<EPI_H_BIASM, bf16, 3>,  cudaFuncAttributeMaxDynamicSharedMemorySize, SMEM_TOTAL);
        cudaFuncSetAttribute(mma_gemm<EPI_F32_SCALE, fp16, 1>, cudaFuncAttributeMaxDynamicSharedMemorySize, SMEM_TOTAL);
        cudaFuncSetAttribute(mma_gemm<EPI_F32, fp16, 1>,       cudaFuncAttributeMaxDynamicSharedMemorySize, SMEM_TOTAL);
        attr_done = true;
    }

    bf16 *Xh, *Xl, *Wqh, *Wql, *Wkh, *Wkl, *Wvh, *Wvl;
    fp16 *Q, *K, *Vt, *P;
    float* S;
    cudaGetSymbolAddress((void**)&Xh,  g_Xh);  cudaGetSymbolAddress((void**)&Xl,  g_Xl);
    cudaGetSymbolAddress((void**)&Wqh, g_Wqh); cudaGetSymbolAddress((void**)&Wql, g_Wql);
    cudaGetSymbolAddress((void**)&Wkh, g_Wkh); cudaGetSymbolAddress((void**)&Wkl, g_Wkl);
    cudaGetSymbolAddress((void**)&Wvh, g_Wvh); cudaGetSymbolAddress((void**)&Wvl, g_Wvl);
    cudaGetSymbolAddress((void**)&Q,   g_Q);   cudaGetSymbolAddress((void**)&K,   g_K);
    cudaGetSymbolAddress((void**)&Vt,  g_Vt);  cudaGetSymbolAddress((void**)&P,   g_P);
    cudaGetSymbolAddress((void**)&S,   g_S);

    // 0) splits
    split_pair4<<<MTOT * DIM / 1024, 256>>>((const float4*)X, Xh, Xl);
    splitT1024<<<DIM * DIM / 256, 256>>>(Wq, Wqh, Wql);
    splitT1024<<<DIM * DIM / 256, 256>>>(Wk, Wkh, Wkl);
    splitT1024<<<DIM * DIM / 256, 256>>>(Wv, Wvh, Wvl);

    // 1) Q = X Wq + bq ; K = X Wk + bk  (fp16 outputs, 3-pass bf16-split)
    mma_gemm<EPI_H_BIASN, bf16, 3><<<dim3(DIM / BN, MTOT / BM, 1), 256, SMEM_TOTAL>>>(
        Xh, Xl, DIM, 0, Wqh, Wql, DIM, 0, bq, 1.f, nullptr, Q, DIM, 0, 5);
    mma_gemm<EPI_H_BIASN, bf16, 3><<<dim3(DIM / BN, MTOT / BM, 1), 256, SMEM_TOTAL>>>(
        Xh, Xl, DIM, 0, Wkh, Wkl, DIM, 0, bk, 1.f, nullptr, K, DIM, 0, 5);
    //    Vt = Wv^T X^T + bv (bias along M); Vt [dim, tokens], fp16
    mma_gemm<EPI_H_BIASM, bf16, 3><<<dim3(MTOT / BN, DIM / BM, 1), 256, SMEM_TOTAL>>>(
        Wvh, Wvl, DIM, 0, Xh, Xl, DIM, 0, bv, 1.f, nullptr, Vt, MTOT, 0, 5);

    // 2) S = (Q K^T) / 32 per batch  (single-pass fp16)
    mma_gemm<EPI_F32_SCALE, fp16, 1><<<dim3(SEQ / BN, SEQ / BM, NB), 256, SMEM_TOTAL>>>(
        Q, nullptr, DIM, (unsigned long long)SEQ * DIM,
        K, nullptr, DIM, (unsigned long long)SEQ * DIM,
        nullptr, 0.03125f, S, nullptr, SEQ, (unsigned long long)SEQ * SEQ, 5);

    // 3) softmax rows -> fp16 P
    softmax_h<<<NB * SEQ, 256>>>(S, P);

    // 4) out = P V per batch (single-pass fp16; B operand = Vt, batch selects cols)
    mma_gemm<EPI_F32, fp16, 1><<<dim3(DIM / BN, SEQ / BM, NB), 256, SMEM_TOTAL>>>(
        P, nullptr, SEQ, (unsigned long long)SEQ * SEQ,
        Vt, nullptr, MTOT, (unsigned long long)SEQ,
        nullptr, 1.f, out, nullptr, DIM, (unsigned long long)SEQ * DIM, 7);
}

// round 6
// speedup vs baseline: 4.3217x; 1.2048x over previous
#include <cuda_runtime.h>
#include <cuda_bf16.h>
#include <cuda_fp16.h>
#include <cstdint>

// Shapes fixed by dataset:
//   X [4,4096,1024] f32 ; Wq/Wk/Wv [1024,1024] ; bq/bk/bv [1024]
//   out[4,4096,1024] = softmax((XWq+bq)(XWk+bk)^T / 32) (XWv+bv)

#define SEQ   4096
#define DIM   1024
#define NB    4
#define MTOT  (NB*SEQ)          // 16384

typedef __half fp16;

// ---------------------------------------------------------------------------
// Device scratch (no allocation allowed)
// ---------------------------------------------------------------------------
__device__ __align__(256) fp16 g_Xh[(size_t)MTOT*DIM], g_Xl[(size_t)MTOT*DIM];
__device__ __align__(256) fp16 g_WqT[DIM*DIM];   // W^T [n,k], fp16
__device__ __align__(256) fp16 g_WkT[DIM*DIM];
__device__ __align__(256) fp16 g_WvT[DIM*DIM];
__device__ __align__(256) fp16 g_Q [(size_t)MTOT*DIM];
__device__ __align__(256) fp16 g_K [(size_t)MTOT*DIM];
__device__ __align__(256) fp16 g_Vt[(size_t)DIM*MTOT];          // V^T [dim, tokens]
__device__ __align__(256) float g_S [(size_t)NB*SEQ*SEQ];
__device__ __align__(256) fp16 g_P [(size_t)NB*SEQ*SEQ];

// ---------------------------------------------------------------------------
// sm_80-class PTX helpers (cp.async / ldmatrix / mma.sync)
// ---------------------------------------------------------------------------
__device__ __forceinline__ uint32_t smem_u32(const void* p) {
    uint32_t a;
    asm("{ .reg .u64 t; cvta.to.shared.u64 t, %1; cvt.u32.u64 %0, t; }" : "=r"(a) : "l"(p));
    return a;
}
__device__ __forceinline__ void cp16(uint32_t dst, const void* src) {
    asm volatile("cp.async.cg.shared.global [%0], [%1], 16;" :: "r"(dst), "l"(src) : "memory");
}
#define CP_COMMIT() asm volatile("cp.async.commit_group;" ::: "memory")
#define CP_WAIT(n)  asm volatile("cp.async.wait_group %0;" :: "n"(n) : "memory")

__device__ __forceinline__ void ldsm4(uint32_t* r, uint32_t addr) {
    asm volatile("ldmatrix.sync.aligned.m8n8.x4.shared.b16 {%0,%1,%2,%3}, [%4];"
                 : "=r"(r[0]), "=r"(r[1]), "=r"(r[2]), "=r"(r[3]) : "r"(addr));
}
__device__ __forceinline__ void mma16816(float* d, const uint32_t* a, uint32_t b0, uint32_t b1) {
    asm volatile(
        "mma.sync.aligned.m16n8k16.row.col.f32.f16.f16.f32 "
        "{%0,%1,%2,%3}, {%4,%5,%6,%7}, {%8,%9}, {%0,%1,%2,%3};"
        : "+f"(d[0]), "+f"(d[1]), "+f"(d[2]), "+f"(d[3])
        : "r"(a[0]), "r"(a[1]), "r"(a[2]), "r"(a[3]), "r"(b0), "r"(b1));
}
__device__ __forceinline__ void split2h(float f, fp16& h, fp16& l) {
    h = __float2half_rn(f);
    l = __float2half_rn(f - __half2float(h));
}

// ---------------------------------------------------------------------------
// GEMM: C[M,N] = scale*(A B^T) (+bias), fp16 operands, f32 accumulate.
// NPASS=2: second pass accumulates A2 B2^T (split correction term).
// Tile 128x128x32, 256 threads (2x4 warps, 64x32 warp tile), 4-stage cp.async.
// ---------------------------------------------------------------------------
#define BM 128
#define BN 128
#define BK 32
#define STAGES 4
#define ROWB 80                        // padded smem row: 32 elts (64B) -> 80B
#define ATILE_B (128*ROWB)             // 10240
#define STAGE_B (2*ATILE_B)            // 20480 (A + B)
#define SMEM_TOTAL (STAGES*STAGE_B)    // 81920

enum { EPI_H_BIASN = 0, EPI_H_BIASM = 1, EPI_F32_SCALE = 2, EPI_F32 = 3 };

__device__ __forceinline__ void load_stage(uint32_t sm, const fp16* pA, int lda,
                                           const fp16* pB, int ldb, int koff, int tid) {
#pragma unroll
    for (int rep = 0; rep < 2; rep++) {
        const int idx = tid + rep * 256;
        const int row = idx >> 2, j = idx & 3;
        cp16(sm + row * ROWB + j * 16, pA + (size_t)row * lda + koff + j * 8);
        cp16(sm + ATILE_B + row * ROWB + j * 16, pB + (size_t)row * ldb + koff + j * 8);
    }
}

template <int MODE, int NPASS>
__global__ void __launch_bounds__(256)
mma_gemm(const fp16* __restrict__ A1, const fp16* __restrict__ A2,
         int lda, unsigned long long strA,
         const fp16* __restrict__ B1, const fp16* __restrict__ B2,
         int ldb, unsigned long long strB,
         const float* __restrict__ bias, float scale,
         float* __restrict__ Cf, fp16* __restrict__ Ch,
         int ldc, unsigned long long strC, int scLog)
{
    extern __shared__ __align__(256) char smem[];
    const uint32_t sbase = smem_u32(smem);
    const int tid = threadIdx.x;
    const int wid = tid >> 5, lane = tid & 31;
    const int warpM = wid >> 2, warpN = wid & 3;      // 2 x 4 warp grid
    const int z = blockIdx.z;
    const int col0 = blockIdx.x * BN, row0 = blockIdx.y * BM;

    const fp16* A1_ = A1 + (size_t)z * strA + (size_t)row0 * lda;
    const fp16* A2_ = (NPASS == 2) ? (A2 + (size_t)z * strA + (size_t)row0 * lda) : A1_;
    const fp16* B1_ = B1 + (size_t)z * strB + (size_t)col0 * ldb;
    const fp16* B2_ = (NPASS == 2) ? (B2 + (size_t)z * strB + (size_t)col0 * ldb) : B1_;

    const int segC = 1 << scLog;        // chunks per pass = K/32
    const int NC = NPASS << scLog;

    float d[4][4][4];
#pragma unroll
    for (int i = 0; i < 4; i++)
#pragma unroll
        for (int j = 0; j < 4; j++)
#pragma unroll
            for (int e = 0; e < 4; e++) d[i][j][e] = 0.f;

    // prologue: stages 0..STAGES-2
#pragma unroll
    for (int s = 0; s < STAGES - 1; s++) {
        const int seg = (NPASS == 1) ? 0 : (s >> scLog);
        const int koff = (s & (segC - 1)) << 5;
        load_stage(sbase + s * STAGE_B, seg ? A2_ : A1_, lda, seg ? B2_ : B1_, ldb, koff, tid);
        CP_COMMIT();
    }

    const int lrow = lane & 15;          // row within 16-row tile
    const int lcolh = lane >> 4;         // k half (0/1)

    for (int c = 0; c < NC; c++) {
        CP_WAIT(STAGES - 2);
        __syncthreads();

        const int cn = c + STAGES - 1;
        if (cn < NC) {
            const int seg = (NPASS == 1) ? 0 : (cn >> scLog);
            const int koff = (cn & (segC - 1)) << 5;
            load_stage(sbase + (cn % STAGES) * STAGE_B, seg ? A2_ : A1_, lda,
                       seg ? B2_ : B1_, ldb, koff, tid);
        }
        CP_COMMIT();

        const uint32_t As = sbase + (c % STAGES) * STAGE_B;
        const uint32_t Bs = As + ATILE_B;

#pragma unroll
        for (int ks = 0; ks < 2; ks++) {
            const int c16 = ks * 2 + lcolh;
            uint32_t a[4][4];
#pragma unroll
            for (int i = 0; i < 4; i++) {
                const int r = warpM * 64 + i * 16 + lrow;
                ldsm4(a[i], As + r * ROWB + c16 * 16);
            }
            uint32_t bfr[2][4];
#pragma unroll
            for (int p = 0; p < 2; p++) {
                const int r = warpN * 32 + p * 16 + lrow;
                ldsm4(bfr[p], Bs + r * ROWB + c16 * 16);
            }
#pragma unroll
            for (int i = 0; i < 4; i++)
#pragma unroll
                for (int j = 0; j < 4; j++) {
                    const int p = j >> 1, s = j & 1;
                    mma16816(d[i][j], a[i], bfr[p][s], bfr[p][s + 2]);
                }
        }
    }

    // ------------------------- epilogue -------------------------
    const int qr = lane >> 2;            // 0..7
    const int qc = (lane & 3) * 2;       // 0,2,4,6
#pragma unroll
    for (int i = 0; i < 4; i++) {
#pragma unroll
        for (int j = 0; j < 4; j++) {
            const int r = row0 + warpM * 64 + i * 16 + qr;
            const int ccol = col0 + warpN * 32 + j * 8 + qc;
#pragma unroll
            for (int h = 0; h < 2; h++) {            // h=0: rows r, h=1: r+8
                const int rr = r + h * 8;
                float f0 = d[i][j][h * 2 + 0];
                float f1 = d[i][j][h * 2 + 1];
                if (MODE == EPI_F32_SCALE || MODE == EPI_F32) {
                    float2 o; o.x = f0 * scale; o.y = f1 * scale;
                    *(float2*)(Cf + (size_t)z * strC + (size_t)rr * ldc + ccol) = o;
                } else {
                    if (MODE == EPI_H_BIASN) { f0 += bias[ccol]; f1 += bias[ccol + 1]; }
                    else                     { f0 += bias[rr];   f1 += bias[rr]; }
                    const size_t off = (size_t)z * strC + (size_t)rr * ldc + ccol;
                    *(__half2*)(Ch + off) = __floats2half2_rn(f0, f1);
                }
            }
        }
    }
}

// ---------------------------------------------------------------------------
// f32 -> fp16 hi/lo split (vectorized)
// ---------------------------------------------------------------------------
__global__ void __launch_bounds__(256) split_pair4(const float4* __restrict__ x,
                                                   fp16* __restrict__ h, fp16* __restrict__ l)
{
    const size_t i = (size_t)blockIdx.x * 256 + threadIdx.x;
    const float4 v = x[i];
    fp16 h0, l0, h1, l1, h2, l2, h3, l3;
    split2h(v.x, h0, l0); split2h(v.y, h1, l1); split2h(v.z, h2, l2); split2h(v.w, h3, l3);
    __half2 ha = __halves2half2(h0, h1), hb = __halves2half2(h2, h3);
    __half2 la = __halves2half2(l0, l1), lb = __halves2half2(l2, l3);
    ((uint2*)h)[i] = make_uint2(*(uint32_t*)&ha, *(uint32_t*)&hb);
    ((uint2*)l)[i] = make_uint2(*(uint32_t*)&la, *(uint32_t*)&lb);
}

// W [K=1024, N=1024] row-major -> transposed fp16 T [N,K]
__global__ void __launch_bounds__(256) splitT1024(const float* __restrict__ W,
                                                  fp16* __restrict__ T)
{
    const int idx = blockIdx.x * 256 + threadIdx.x;
    const int k = idx >> 10, n = idx & 1023;
    T[n * 1024 + k] = __float2half_rn(W[idx]);
}

// ---------------------------------------------------------------------------
// Row softmax (len 4096) -> fp16 probabilities
// ---------------------------------------------------------------------------
__global__ void __launch_bounds__(256) softmax_h(const float* __restrict__ S,
                                                 fp16* __restrict__ P)
{
    const float4* p = (const float4*)(S + (size_t)blockIdx.x * SEQ);
    const int tid = threadIdx.x;

    float4 v[4];
    float mx = -3.4e38f;
#pragma unroll
    for (int i = 0; i < 4; i++) {
        v[i] = p[tid + i * 256];
        mx = fmaxf(mx, fmaxf(fmaxf(v[i].x, v[i].y), fmaxf(v[i].z, v[i].w)));
    }
    __shared__ float red[8];
#pragma unroll
    for (int o = 16; o > 0; o >>= 1) mx = fmaxf(mx, __shfl_xor_sync(0xffffffffu, mx, o));
    if ((tid & 31) == 0) red[tid >> 5] = mx;
    __syncthreads();
    float bmx = red[0];
#pragma unroll
    for (int w = 1; w < 8; w++) bmx = fmaxf(bmx, red[w]);
    __syncthreads();

    float s = 0.f;
#pragma unroll
    for (int i = 0; i < 4; i++) {
        v[i].x = __expf(v[i].x - bmx);
        v[i].y = __expf(v[i].y - bmx);
        v[i].z = __expf(v[i].z - bmx);
        v[i].w = __expf(v[i].w - bmx);
        s += v[i].x + v[i].y + v[i].z + v[i].w;
    }
#pragma unroll
    for (int o = 16; o > 0; o >>= 1) s += __shfl_xor_sync(0xffffffffu, s, o);
    if ((tid & 31) == 0) red[tid >> 5] = s;
    __syncthreads();
    float bs = 0.f;
#pragma unroll
    for (int w = 0; w < 8; w++) bs += red[w];
    const float inv = __frcp_rn(bs);

    uint2* op = (uint2*)(P + (size_t)blockIdx.x * SEQ);
#pragma unroll
    for (int i = 0; i < 4; i++) {
        __half2 a = __floats2half2_rn(v[i].x * inv, v[i].y * inv);
        __half2 b = __floats2half2_rn(v[i].z * inv, v[i].w * inv);
        op[tid + i * 256] = make_uint2(*(uint32_t*)&a, *(uint32_t*)&b);
    }
}

// ---------------------------------------------------------------------------
// kernel_launch
// ---------------------------------------------------------------------------
extern "C" void kernel_launch(void* const* d_in, const int* in_sizes, int n_in,
                              void* d_out, int out_size)
{
    const float* X  = (const float*)d_in[0];
    const float* Wq = (const float*)d_in[1];
    const float* Wk = (const float*)d_in[2];
    const float* Wv = (const float*)d_in[3];
    const float* bq = (const float*)d_in[4];
    const float* bk = (const float*)d_in[5];
    const float* bv = (const float*)d_in[6];
    float* out = (float*)d_out;

    static bool attr_done = false;
    if (!attr_done) {
        cudaFuncSetAttribute(mma_gemm<EPI_H_BIASN, 2>,  cudaFuncAttributeMaxDynamicSharedMemorySize, SMEM_TOTAL);
        cudaFuncSetAttribute(mma_gemm<EPI_H_BIASM, 2>,  cudaFuncAttributeMaxDynamicSharedMemorySize, SMEM_TOTAL);
        cudaFuncSetAttribute(mma_gemm<EPI_F32_SCALE, 1>, cudaFuncAttributeMaxDynamicSharedMemorySize, SMEM_TOTAL);
        cudaFuncSetAttribute(mma_gemm<EPI_F32, 1>,       cudaFuncAttributeMaxDynamicSharedMemorySize, SMEM_TOTAL);
        attr_done = true;
    }

    fp16 *Xh, *Xl, *WqT, *WkT, *WvT, *Q, *K, *Vt, *P;
    float* S;
    cudaGetSymbolAddress((void**)&Xh,  g_Xh);  cudaGetSymbolAddress((void**)&Xl,  g_Xl);
    cudaGetSymbolAddress((void**)&WqT, g_WqT); cudaGetSymbolAddress((void**)&WkT, g_WkT);
    cudaGetSymbolAddress((void**)&WvT, g_WvT);
    cudaGetSymbolAddress((void**)&Q,   g_Q);   cudaGetSymbolAddress((void**)&K,   g_K);
    cudaGetSymbolAddress((void**)&Vt,  g_Vt);  cudaGetSymbolAddress((void**)&P,   g_P);
    cudaGetSymbolAddress((void**)&S,   g_S);

    // 0) splits: X -> fp16 hi/lo pair; W -> transposed fp16
    split_pair4<<<MTOT * DIM / 1024, 256>>>((const float4*)X, Xh, Xl);
    splitT1024<<<DIM * DIM / 256, 256>>>(Wq, WqT);
    splitT1024<<<DIM * DIM / 256, 256>>>(Wk, WkT);
    splitT1024<<<DIM * DIM / 256, 256>>>(Wv, WvT);

    // 1) Q = X Wq + bq ; K = X Wk + bk   (2-pass: Xh*W + Xl*W)
    mma_gemm<EPI_H_BIASN, 2><<<dim3(DIM / BN, MTOT / BM, 1), 256, SMEM_TOTAL>>>(
        Xh, Xl, DIM, 0, WqT, WqT, DIM, 0, bq, 1.f, nullptr, Q, DIM, 0, 5);
    mma_gemm<EPI_H_BIASN, 2><<<dim3(DIM / BN, MTOT / BM, 1), 256, SMEM_TOTAL>>>(
        Xh, Xl, DIM, 0, WkT, WkT, DIM, 0, bk, 1.f, nullptr, K, DIM, 0, 5);
    //    Vt = Wv^T X^T + bv (bias along M); 2-pass: Wv*Xh + Wv*Xl
    mma_gemm<EPI_H_BIASM, 2><<<dim3(MTOT / BN, DIM / BM, 1), 256, SMEM_TOTAL>>>(
        WvT, WvT, DIM, 0, Xh, Xl, DIM, 0, bv, 1.f, nullptr, Vt, MTOT, 0, 5);

    // 2) S = (Q K^T) / 32 per batch  (single-pass fp16)
    mma_gemm<EPI_F32_SCALE, 1><<<dim3(SEQ / BN, SEQ / BM, NB), 256, SMEM_TOTAL>>>(
        Q, nullptr, DIM, (unsigned long long)SEQ * DIM,
        K, nullptr, DIM, (unsigned long long)SEQ * DIM,
        nullptr, 0.03125f, S, nullptr, SEQ, (unsigned long long)SEQ * SEQ, 5);

    // 3) softmax rows -> fp16 P
    softmax_h<<<NB * SEQ, 256>>>(S, P);

    // 4) out = P V per batch (single-pass fp16; B operand = Vt, batch selects cols)
    mma_gemm<EPI_F32, 1><<<dim3(DIM / BN, SEQ / BM, NB), 256, SMEM_TOTAL>>>(
        P, nullptr, SEQ, (unsigned long long)SEQ * SEQ,
        Vt, nullptr, MTOT, (unsigned long long)SEQ,
        nullptr, 1.f, out, nullptr, DIM, (unsigned long long)SEQ * DIM, 7);
}

// round 9
// speedup vs baseline: 5.3078x; 1.2282x over previous
#include <cuda_runtime.h>
#include <cuda_bf16.h>
#include <cuda_fp16.h>
#include <cstdint>

// Shapes fixed by dataset:
//   X [4,4096,1024] f32 ; Wq/Wk/Wv [1024,1024] ; bq/bk/bv [1024]
//   out[4,4096,1024] = softmax((XWq+bq)(XWk+bk)^T / 32) (XWv+bv)

#define SEQ   4096
#define DIM   1024
#define NB    4
#define MTOT  (NB*SEQ)          // 16384

typedef __half fp16;

// ---------------------------------------------------------------------------
// Device scratch (no allocation allowed)
// ---------------------------------------------------------------------------
__device__ __align__(256) fp16 g_X [(size_t)MTOT*DIM];
__device__ __align__(256) fp16 g_WqT[DIM*DIM];   // W^T [n,k], fp16
__device__ __align__(256) fp16 g_WkT[DIM*DIM];
__device__ __align__(256) fp16 g_WvT[DIM*DIM];
__device__ __align__(256) fp16 g_Q [(size_t)MTOT*DIM];
__device__ __align__(256) fp16 g_K [(size_t)MTOT*DIM];
__device__ __align__(256) fp16 g_Vt[(size_t)DIM*MTOT];          // V^T [dim, tokens]
__device__ __align__(256) float g_S [(size_t)NB*SEQ*SEQ];
__device__ __align__(256) fp16 g_P [(size_t)NB*SEQ*SEQ];

// ---------------------------------------------------------------------------
// sm_80-class PTX helpers (cp.async / ldmatrix / mma.sync)
// ---------------------------------------------------------------------------
__device__ __forceinline__ uint32_t smem_u32(const void* p) {
    uint32_t a;
    asm("{ .reg .u64 t; cvta.to.shared.u64 t, %1; cvt.u32.u64 %0, t; }" : "=r"(a) : "l"(p));
    return a;
}
__device__ __forceinline__ void cp16(uint32_t dst, const void* src) {
    asm volatile("cp.async.cg.shared.global [%0], [%1], 16;" :: "r"(dst), "l"(src) : "memory");
}
#define CP_COMMIT() asm volatile("cp.async.commit_group;" ::: "memory")
#define CP_WAIT(n)  asm volatile("cp.async.wait_group %0;" :: "n"(n) : "memory")

__device__ __forceinline__ void ldsm4(uint32_t* r, uint32_t addr) {
    asm volatile("ldmatrix.sync.aligned.m8n8.x4.shared.b16 {%0,%1,%2,%3}, [%4];"
                 : "=r"(r[0]), "=r"(r[1]), "=r"(r[2]), "=r"(r[3]) : "r"(addr));
}
__device__ __forceinline__ void mma16816(float* d, const uint32_t* a, uint32_t b0, uint32_t b1) {
    asm volatile(
        "mma.sync.aligned.m16n8k16.row.col.f32.f16.f16.f32 "
        "{%0,%1,%2,%3}, {%4,%5,%6,%7}, {%8,%9}, {%0,%1,%2,%3};"
        : "+f"(d[0]), "+f"(d[1]), "+f"(d[2]), "+f"(d[3])
        : "r"(a[0]), "r"(a[1]), "r"(a[2]), "r"(a[3]), "r"(b0), "r"(b1));
}

// ---------------------------------------------------------------------------
// GEMM: C[M,N] = scale*(A B^T) (+bias), fp16 operands, f32 accumulate.
// Tile 128x128x32, 256 threads (2x4 warps, 64x32 warp tile), 4-stage cp.async.
// ---------------------------------------------------------------------------
#define BM 128
#define BN 128
#define BK 32
#define STAGES 4
#define ROWB 80                        // padded smem row: 32 elts (64B) -> 80B
#define ATILE_B (128*ROWB)             // 10240
#define STAGE_B (2*ATILE_B)            // 20480 (A + B)
#define SMEM_TOTAL (STAGES*STAGE_B)    // 81920

enum { EPI_H_BIASN = 0, EPI_H_BIASM = 1, EPI_F32_SCALE = 2, EPI_F32 = 3 };

__device__ __forceinline__ void load_stage(uint32_t sm, const fp16* pA, int lda,
                                           const fp16* pB, int ldb, int koff, int tid) {
#pragma unroll
    for (int rep = 0; rep < 2; rep++) {
        const int idx = tid + rep * 256;
        const int row = idx >> 2, j = idx & 3;
        cp16(sm + row * ROWB + j * 16, pA + (size_t)row * lda + koff + j * 8);
        cp16(sm + ATILE_B + row * ROWB + j * 16, pB + (size_t)row * ldb + koff + j * 8);
    }
}

template <int MODE>
__global__ void __launch_bounds__(256)
mma_gemm(const fp16* __restrict__ A1, int lda, unsigned long long strA,
         const fp16* __restrict__ B1, int ldb, unsigned long long strB,
         const float* __restrict__ bias, float scale,
         float* __restrict__ Cf, fp16* __restrict__ Ch,
         int ldc, unsigned long long strC, int NC)
{
    extern __shared__ __align__(256) char smem[];
    const uint32_t sbase = smem_u32(smem);
    const int tid = threadIdx.x;
    const int wid = tid >> 5, lane = tid & 31;
    const int warpM = wid >> 2, warpN = wid & 3;      // 2 x 4 warp grid
    const int z = blockIdx.z;
    const int col0 = blockIdx.x * BN, row0 = blockIdx.y * BM;

    const fp16* A1_ = A1 + (size_t)z * strA + (size_t)row0 * lda;
    const fp16* B1_ = B1 + (size_t)z * strB + (size_t)col0 * ldb;

    float d[4][4][4];
#pragma unroll
    for (int i = 0; i < 4; i++)
#pragma unroll
        for (int j = 0; j < 4; j++)
#pragma unroll
            for (int e = 0; e < 4; e++) d[i][j][e] = 0.f;

    // prologue: stages 0..STAGES-2
#pragma unroll
    for (int s = 0; s < STAGES - 1; s++) {
        load_stage(sbase + s * STAGE_B, A1_, lda, B1_, ldb, s << 5, tid);
        CP_COMMIT();
    }

    const int lrow = lane & 15;          // row within 16-row tile
    const int lcolh = lane >> 4;         // k half (0/1)

    for (int c = 0; c < NC; c++) {
        CP_WAIT(STAGES - 2);
        __syncthreads();

        const int cn = c + STAGES - 1;
        if (cn < NC) {
            load_stage(sbase + (cn % STAGES) * STAGE_B, A1_, lda, B1_, ldb, cn << 5, tid);
        }
        CP_COMMIT();

        const uint32_t As = sbase + (c % STAGES) * STAGE_B;
        const uint32_t Bs = As + ATILE_B;

#pragma unroll
        for (int ks = 0; ks < 2; ks++) {
            const int c16 = ks * 2 + lcolh;
            uint32_t a[4][4];
#pragma unroll
            for (int i = 0; i < 4; i++) {
                const int r = warpM * 64 + i * 16 + lrow;
                ldsm4(a[i], As + r * ROWB + c16 * 16);
            }
            uint32_t bfr[2][4];
#pragma unroll
            for (int p = 0; p < 2; p++) {
                const int r = warpN * 32 + p * 16 + lrow;
                ldsm4(bfr[p], Bs + r * ROWB + c16 * 16);
            }
#pragma unroll
            for (int i = 0; i < 4; i++)
#pragma unroll
                for (int j = 0; j < 4; j++) {
                    const int p = j >> 1, s = j & 1;
                    mma16816(d[i][j], a[i], bfr[p][s], bfr[p][s + 2]);
                }
        }
    }

    // ------------------------- epilogue -------------------------
    const int qr = lane >> 2;            // 0..7
    const int qc = (lane & 3) * 2;       // 0,2,4,6
#pragma unroll
    for (int i = 0; i < 4; i++) {
#pragma unroll
        for (int j = 0; j < 4; j++) {
            const int r = row0 + warpM * 64 + i * 16 + qr;
            const int ccol = col0 + warpN * 32 + j * 8 + qc;
#pragma unroll
            for (int h = 0; h < 2; h++) {            // h=0: rows r, h=1: r+8
                const int rr = r + h * 8;
                float f0 = d[i][j][h * 2 + 0];
                float f1 = d[i][j][h * 2 + 1];
                if (MODE == EPI_F32_SCALE || MODE == EPI_F32) {
                    float2 o; o.x = f0 * scale; o.y = f1 * scale;
                    *(float2*)(Cf + (size_t)z * strC + (size_t)rr * ldc + ccol) = o;
                } else {
                    if (MODE == EPI_H_BIASN) { f0 += bias[ccol]; f1 += bias[ccol + 1]; }
                    else                     { f0 += bias[rr];   f1 += bias[rr]; }
                    const size_t off = (size_t)z * strC + (size_t)rr * ldc + ccol;
                    *(__half2*)(Ch + off) = __floats2half2_rn(f0, f1);
                }
            }
        }
    }
}

// ---------------------------------------------------------------------------
// f32 -> fp16 convert (vectorized, 4 elems/thread)
// ---------------------------------------------------------------------------
__global__ void __launch_bounds__(256) cvt_half4(const float4* __restrict__ x,
                                                 fp16* __restrict__ h)
{
    const size_t i = (size_t)blockIdx.x * 256 + threadIdx.x;
    const float4 v = x[i];
    __half2 a = __floats2half2_rn(v.x, v.y);
    __half2 b = __floats2half2_rn(v.z, v.w);
    ((uint2*)h)[i] = make_uint2(*(uint32_t*)&a, *(uint32_t*)&b);
}

// W [K=1024, N=1024] row-major -> transposed fp16 T [N,K]
__global__ void __launch_bounds__(256) cvtT1024(const float* __restrict__ W,
                                                fp16* __restrict__ T)
{
    const int idx = blockIdx.x * 256 + threadIdx.x;
    const int k = idx >> 10, n = idx & 1023;
    T[n * 1024 + k] = __float2half_rn(W[idx]);
}

// ---------------------------------------------------------------------------
// Row softmax (len 4096) -> fp16 probabilities
// ---------------------------------------------------------------------------
__global__ void __launch_bounds__(256) softmax_h(const float* __restrict__ S,
                                                 fp16* __restrict__ P)
{
    const float4* p = (const float4*)(S + (size_t)blockIdx.x * SEQ);
    const int tid = threadIdx.x;

    float4 v[4];
    float mx = -3.4e38f;
#pragma unroll
    for (int i = 0; i < 4; i++) {
        v[i] = p[tid + i * 256];
        mx = fmaxf(mx, fmaxf(fmaxf(v[i].x, v[i].y), fmaxf(v[i].z, v[i].w)));
    }
    __shared__ float red[8];
#pragma unroll
    for (int o = 16; o > 0; o >>= 1) mx = fmaxf(mx, __shfl_xor_sync(0xffffffffu, mx, o));
    if ((tid & 31) == 0) red[tid >> 5] = mx;
    __syncthreads();
    float bmx = red[0];
#pragma unroll
    for (int w = 1; w < 8; w++) bmx = fmaxf(bmx, red[w]);
    __syncthreads();

    float s = 0.f;
#pragma unroll
    for (int i = 0; i < 4; i++) {
        v[i].x = __expf(v[i].x - bmx);
        v[i].y = __expf(v[i].y - bmx);
        v[i].z = __expf(v[i].z - bmx);
        v[i].w = __expf(v[i].w - bmx);
        s += v[i].x + v[i].y + v[i].z + v[i].w;
    }
#pragma unroll
    for (int o = 16; o > 0; o >>= 1) s += __shfl_xor_sync(0xffffffffu, s, o);
    if ((tid & 31) == 0) red[tid >> 5] = s;
    __syncthreads();
    float bs = 0.f;
#pragma unroll
    for (int w = 0; w < 8; w++) bs += red[w];
    const float inv = __frcp_rn(bs);

    uint2* op = (uint2*)(P + (size_t)blockIdx.x * SEQ);
#pragma unroll
    for (int i = 0; i < 4; i++) {
        __half2 a = __floats2half2_rn(v[i].x * inv, v[i].y * inv);
        __half2 b = __floats2half2_rn(v[i].z * inv, v[i].w * inv);
        op[tid + i * 256] = make_uint2(*(uint32_t*)&a, *(uint32_t*)&b);
    }
}

// ---------------------------------------------------------------------------
// kernel_launch
// ---------------------------------------------------------------------------
extern "C" void kernel_launch(void* const* d_in, const int* in_sizes, int n_in,
                              void* d_out, int out_size)
{
    const float* X  = (const float*)d_in[0];
    const float* Wq = (const float*)d_in[1];
    const float* Wk = (const float*)d_in[2];
    const float* Wv = (const float*)d_in[3];
    const float* bq = (const float*)d_in[4];
    const float* bk = (const float*)d_in[5];
    const float* bv = (const float*)d_in[6];
    float* out = (float*)d_out;

    // Idempotent, capture-safe; no static guards per harness rules.
    cudaFuncSetAttribute(mma_gemm<EPI_H_BIASN>,  cudaFuncAttributeMaxDynamicSharedMemorySize, SMEM_TOTAL);
    cudaFuncSetAttribute(mma_gemm<EPI_H_BIASM>,  cudaFuncAttributeMaxDynamicSharedMemorySize, SMEM_TOTAL);
    cudaFuncSetAttribute(mma_gemm<EPI_F32_SCALE>, cudaFuncAttributeMaxDynamicSharedMemorySize, SMEM_TOTAL);
    cudaFuncSetAttribute(mma_gemm<EPI_F32>,       cudaFuncAttributeMaxDynamicSharedMemorySize, SMEM_TOTAL);

    fp16 *Xf, *WqT, *WkT, *WvT, *Q, *K, *Vt, *P;
    float* S;
    cudaGetSymbolAddress((void**)&Xf,  g_X);
    cudaGetSymbolAddress((void**)&WqT, g_WqT); cudaGetSymbolAddress((void**)&WkT, g_WkT);
    cudaGetSymbolAddress((void**)&WvT, g_WvT);
    cudaGetSymbolAddress((void**)&Q,   g_Q);   cudaGetSymbolAddress((void**)&K,   g_K);
    cudaGetSymbolAddress((void**)&Vt,  g_Vt);  cudaGetSymbolAddress((void**)&P,   g_P);
    cudaGetSymbolAddress((void**)&S,   g_S);

    // 0) converts: X -> fp16; W -> transposed fp16
    cvt_half4<<<MTOT * DIM / 1024, 256>>>((const float4*)X, Xf);
    cvtT1024<<<DIM * DIM / 256, 256>>>(Wq, WqT);
    cvtT1024<<<DIM * DIM / 256, 256>>>(Wk, WkT);
    cvtT1024<<<DIM * DIM / 256, 256>>>(Wv, WvT);

    // 1) Q = X Wq + bq ; K = X Wk + bk  (single-pass fp16)
    mma_gemm<EPI_H_BIASN><<<dim3(DIM / BN, MTOT / BM, 1), 256, SMEM_TOTAL>>>(
        Xf, DIM, 0, WqT, DIM, 0, bq, 1.f, nullptr, Q, DIM, 0, DIM / BK);
    mma_gemm<EPI_H_BIASN><<<dim3(DIM / BN, MTOT / BM, 1), 256, SMEM_TOTAL>>>(
        Xf, DIM, 0, WkT, DIM, 0, bk, 1.f, nullptr, K, DIM, 0, DIM / BK);
    //    Vt = Wv^T X^T + bv (bias along M); Vt [dim, tokens]
    mma_gemm<EPI_H_BIASM><<<dim3(MTOT / BN, DIM / BM, 1), 256, SMEM_TOTAL>>>(
        WvT, DIM, 0, Xf, DIM, 0, bv, 1.f, nullptr, Vt, MTOT, 0, DIM / BK);

    // 2) S = (Q K^T) / 32 per batch
    mma_gemm<EPI_F32_SCALE><<<dim3(SEQ / BN, SEQ / BM, NB), 256, SMEM_TOTAL>>>(
        Q, DIM, (unsigned long long)SEQ * DIM,
        K, DIM, (unsigned long long)SEQ * DIM,
        nullptr, 0.03125f, S, nullptr, SEQ, (unsigned long long)SEQ * SEQ, DIM / BK);

    // 3) softmax rows -> fp16 P
    softmax_h<<<NB * SEQ, 256>>>(S, P);

    // 4) out = P V per batch (B operand = Vt, batch selects column block)
    mma_gemm<EPI_F32><<<dim3(DIM / BN, SEQ / BM, NB), 256, SMEM_TOTAL>>>(
        P, SEQ, (unsigned long long)SEQ * SEQ,
        Vt, MTOT, (unsigned long long)SEQ,
        nullptr, 1.f, out, nullptr, DIM, (unsigned long long)SEQ * DIM, SEQ / BK);
}